// round 3
// baseline (speedup 1.0000x reference)
#include <cuda_runtime.h>
#include <cuda_bf16.h>
#include <math.h>

// ---------------------------------------------------------------------------
// PhotonicDelayReservoirAdaptive — sparse delay-tap reservoir scan, sm_103a.
//
//   fb[b,s]  = sum_k softmax(tapw)[k] * sum_r h[b, t-d_k, r] * W_fb[k,r,s]
//   h_new    = 0.9*h + 0.1*tanh(x[b,t]*W_in[s] + fb[b,s] + bias[s])
//   out[b,t,s] = h_new         (h_{t-d} == 0 for t-d < 0)
//
// W_fb is ~10% dense (masked at construction) -> per-output-column CSR with
// the softmax tap weight folded into each stored value, index = k*256+r into
// the concatenated 1280-entry delayed-state vector.
//
// Mapping: 16 clusters x 8 CTAs. Cluster c owns batches 4c..4c+3. CTA rank r
// owns output columns 32r..32r+31 and keeps that CSR slice in SMEM. State
// history lives in the output buffer (row t written once at step t, read at
// t+{1,4,24,96,168}). All tap reads use __ldcg (L1 bypass); cross-CTA
// ordering via split barrier.cluster arrive(release)/wait(acquire). Taps
// d>=4 are loaded BEFORE the wait (visible since >=3 barriers ago); only the
// tap-1 row is post-barrier critical. Hist is staged batch-packed (float4)
// so one LDS.128 gather serves all 4 batches.
// ---------------------------------------------------------------------------

#define T_LEN      2048
#define R_DIM      256
#define N_TAPS     5
#define RANKS      8            // CTAs per cluster
#define COLS_PER   32           // output columns per CTA
#define BATCH_PER  4            // batches per cluster
#define N_CLUSTERS 16
#define CAP        5120         // padded CSR entries per rank slice (mean 4096+pad)
#define NTHREADS   256

// SMEM layout (dynamic):
//   [0, 20480)                 float4 hist[1280]   (batch-packed delayed states)
//   [20480, 61440)             uint2  csr[CAP]     ({f32 val, idx})
//   [61440, 94208)             float  xs[2048*4]   (x for the 4 batches)
//   [94208, 94208+136)         int    off[33] + pad
#define SMEM_HIST  0
#define SMEM_CSR   20480
#define SMEM_XS    (20480 + 40960)
#define SMEM_OFF   (20480 + 40960 + 32768)
#define SMEM_BYTES (SMEM_OFF + 256)

__device__ uint2 g_entries[RANKS * CAP];
__device__ int   g_off[RANKS * 33];

// ---------------------------------------------------------------------------
// Builder: 1 CTA, 256 threads, thread = output column s. Two coalesced passes
// over W_fb (consecutive s across lanes => 128B lines). Deterministic order
// (k-major, then r). Each column's list padded to a multiple of 8 so the
// 8-way nnz split in the main kernel has uniform trip counts.
// ---------------------------------------------------------------------------
__global__ void build_csr_kernel(const float* __restrict__ W_fb,
                                 const float* __restrict__ tap_weights) {
    __shared__ float tw[N_TAPS];
    __shared__ int   pcnt[R_DIM];
    __shared__ int   loff[R_DIM];

    const int s = threadIdx.x;

    if (s == 0) {
        float m = tap_weights[0];
        #pragma unroll
        for (int k = 1; k < N_TAPS; k++) m = fmaxf(m, tap_weights[k]);
        float e[N_TAPS];
        float sum = 0.f;
        #pragma unroll
        for (int k = 0; k < N_TAPS; k++) { e[k] = expf(tap_weights[k] - m); sum += e[k]; }
        #pragma unroll
        for (int k = 0; k < N_TAPS; k++) tw[k] = e[k] / sum;
    }

    // pass 1: count nnz in column s
    int cnt = 0;
    for (int k = 0; k < N_TAPS; k++) {
        #pragma unroll 8
        for (int r = 0; r < R_DIM; r++)
            cnt += (W_fb[(k * R_DIM + r) * R_DIM + s] != 0.f) ? 1 : 0;
    }
    pcnt[s] = (cnt + 7) & ~7;   // pad to multiple of 8
    __syncthreads();

    // per-rank exclusive scan over its 32 columns (8 scanner threads)
    if (s < RANKS) {
        int off = 0;
        for (int c = 0; c < COLS_PER; c++) {
            int col = s * COLS_PER + c;
            loff[col] = off;
            g_off[s * 33 + c] = off;
            off += pcnt[col];
        }
        g_off[s * 33 + 32] = off;
    }
    __syncthreads();

    // pass 2: emit entries (tap weight folded), pad with zeros
    const int rank = s >> 5;
    int p = loff[s];
    const int pend = p + pcnt[s];
    if (pend <= CAP) {
        for (int k = 0; k < N_TAPS; k++) {
            const float twk = tw[k];
            for (int r = 0; r < R_DIM; r++) {
                float v = W_fb[(k * R_DIM + r) * R_DIM + s];
                if (v != 0.f) {
                    g_entries[rank * CAP + p] =
                        make_uint2(__float_as_uint(v * twk), (unsigned)(k * R_DIM + r));
                    p++;
                }
            }
        }
        for (; p < pend; p++) g_entries[rank * CAP + p] = make_uint2(0u, 0u);
    }
}

// ---------------------------------------------------------------------------
// Main sequential-scan kernel.
// ---------------------------------------------------------------------------
__global__ void __cluster_dims__(RANKS, 1, 1) __launch_bounds__(NTHREADS, 1)
reservoir_kernel(const float* __restrict__ x,
                 const float* __restrict__ W_in,
                 const float* __restrict__ bias,
                 float* __restrict__ out) {
    extern __shared__ char smem_raw[];
    float4* hist = (float4*)(smem_raw + SMEM_HIST);   // [1280] batch-packed
    uint2*  csr  = (uint2*) (smem_raw + SMEM_CSR);    // [CAP]
    float*  xs   = (float*) (smem_raw + SMEM_XS);     // [2048*4], xs[t*4+bb]
    int*    off  = (int*)   (smem_raw + SMEM_OFF);    // [33]

    const int tid  = threadIdx.x;
    const unsigned rank = blockIdx.x & (RANKS - 1);   // == cluster cta rank
    const unsigned cid  = blockIdx.x >> 3;
    const int b0 = (int)cid * BATCH_PER;

    // ---- prologue: stage CSR slice, offsets, x rows ----
    if (tid < 33) off[tid] = g_off[rank * 33 + tid];
    for (int i = tid; i < CAP; i += NTHREADS)
        csr[i] = g_entries[rank * CAP + i];
    for (int tt = tid; tt < T_LEN; tt += NTHREADS) {
        float4 xv;
        xv.x = x[(size_t)(b0 + 0) * T_LEN + tt];
        xv.y = x[(size_t)(b0 + 1) * T_LEN + tt];
        xv.z = x[(size_t)(b0 + 2) * T_LEN + tt];
        xv.w = x[(size_t)(b0 + 3) * T_LEN + tt];
        *(float4*)(xs + tt * 4) = xv;
    }

    const int colg  = tid >> 3;                 // 0..31: column within slice
    const int lane8 = tid & 7;                  // 8-way nnz split
    const int s     = (int)rank * COLS_PER + colg;
    const float w_in_s = W_in[s];
    const float bias_s = bias[s];
    float4 h = make_float4(0.f, 0.f, 0.f, 0.f); // owned state, 4 batches

    __syncthreads();
    const int my_off = off[colg];
    const int my_end = off[colg + 1];

    // per-thread staging row addresses: r = tid
    const size_t bstride = (size_t)T_LEN * R_DIM;
    const float* outr0 = out + (size_t)b0 * bstride + tid;

    asm volatile("barrier.cluster.arrive.aligned;" ::: "memory");

    for (int t = 0; t < T_LEN; t++) {
        float ebuf[N_TAPS][BATCH_PER];

        // taps d>=4: rows visible since >= 3 barriers ago -> load pre-wait
        const int dl1 = t - 4, dl2 = t - 24, dl3 = t - 96, dl4 = t - 168;
        #pragma unroll
        for (int bb = 0; bb < BATCH_PER; bb++) {
            const float* base = outr0 + (size_t)bb * bstride;
            ebuf[1][bb] = (dl1 >= 0) ? __ldcg(base + (size_t)dl1 * R_DIM) : 0.f;
            ebuf[2][bb] = (dl2 >= 0) ? __ldcg(base + (size_t)dl2 * R_DIM) : 0.f;
            ebuf[3][bb] = (dl3 >= 0) ? __ldcg(base + (size_t)dl3 * R_DIM) : 0.f;
            ebuf[4][bb] = (dl4 >= 0) ? __ldcg(base + (size_t)dl4 * R_DIM) : 0.f;
        }

        asm volatile("barrier.cluster.wait.aligned;" ::: "memory");

        // tap d=1: row t-1 just became visible
        {
            const int d0 = t - 1;
            #pragma unroll
            for (int bb = 0; bb < BATCH_PER; bb++) {
                const float* base = outr0 + (size_t)bb * bstride;
                ebuf[0][bb] = (d0 >= 0) ? __ldcg(base + (size_t)d0 * R_DIM) : 0.f;
            }
        }

        // stage batch-packed hist
        #pragma unroll
        for (int k = 0; k < N_TAPS; k++)
            hist[k * R_DIM + tid] =
                make_float4(ebuf[k][0], ebuf[k][1], ebuf[k][2], ebuf[k][3]);
        __syncthreads();

        // sparse feedback: 8 threads split column s's nnz list
        float4 acc = make_float4(0.f, 0.f, 0.f, 0.f);
        for (int j = my_off + lane8; j < my_end; j += 8) {
            const uint2 en = csr[j];
            const float v = __uint_as_float(en.x);
            const float4 hv = hist[en.y];
            acc.x = fmaf(v, hv.x, acc.x);
            acc.y = fmaf(v, hv.y, acc.y);
            acc.z = fmaf(v, hv.z, acc.z);
            acc.w = fmaf(v, hv.w, acc.w);
        }

        // reduce across the 8-thread group
        #pragma unroll
        for (int m = 1; m < 8; m <<= 1) {
            acc.x += __shfl_xor_sync(0xffffffffu, acc.x, m);
            acc.y += __shfl_xor_sync(0xffffffffu, acc.y, m);
            acc.z += __shfl_xor_sync(0xffffffffu, acc.z, m);
            acc.w += __shfl_xor_sync(0xffffffffu, acc.w, m);
        }

        // owner thread: leaky tanh update + coalesced store of row t
        if (lane8 == 0) {
            const float4 xv = *(const float4*)(xs + t * 4);
            h.x = 0.9f * h.x + 0.1f * tanhf(fmaf(xv.x, w_in_s, acc.x) + bias_s);
            h.y = 0.9f * h.y + 0.1f * tanhf(fmaf(xv.y, w_in_s, acc.y) + bias_s);
            h.z = 0.9f * h.z + 0.1f * tanhf(fmaf(xv.z, w_in_s, acc.z) + bias_s);
            h.w = 0.9f * h.w + 0.1f * tanhf(fmaf(xv.w, w_in_s, acc.w) + bias_s);
            float* wbase = out + (size_t)t * R_DIM + s;
            wbase[(size_t)(b0 + 0) * bstride] = h.x;
            wbase[(size_t)(b0 + 1) * bstride] = h.y;
            wbase[(size_t)(b0 + 2) * bstride] = h.z;
            wbase[(size_t)(b0 + 3) * bstride] = h.w;
        }

        // release row t to the cluster
        asm volatile("barrier.cluster.arrive.aligned;" ::: "memory");
    }
    asm volatile("barrier.cluster.wait.aligned;" ::: "memory");
}

// ---------------------------------------------------------------------------
extern "C" void kernel_launch(void* const* d_in, const int* in_sizes, int n_in,
                              void* d_out, int out_size) {
    const float* x           = (const float*)d_in[0];  // (64, 2048, 1)
    const float* W_in        = (const float*)d_in[1];  // (256, 1)
    const float* W_fb        = (const float*)d_in[2];  // (5, 256, 256)
    const float* tap_weights = (const float*)d_in[3];  // (5,)
    const float* bias        = (const float*)d_in[4];  // (256,)
    float* out = (float*)d_out;                        // (64, 2048, 256)

    (void)in_sizes; (void)n_in; (void)out_size;

    cudaFuncSetAttribute(reservoir_kernel,
                         cudaFuncAttributeMaxDynamicSharedMemorySize, SMEM_BYTES);

    build_csr_kernel<<<1, NTHREADS>>>(W_fb, tap_weights);
    reservoir_kernel<<<N_CLUSTERS * RANKS, NTHREADS, SMEM_BYTES>>>(x, W_in, bias, out);
}